// round 13
// baseline (speedup 1.0000x reference)
#include <cuda_runtime.h>
#include <cuda_bf16.h>

typedef unsigned int u32;
#define FULLMASK 0xffffffffu

__device__ __forceinline__ float silu_f(float x){
    return __fdividef(x, 1.0f + __expf(-x));
}

__device__ __forceinline__ u32 smem_u32(const void* p){
    u32 a;
    asm("{ .reg .u64 t; cvta.to.shared.u64 t, %1; cvt.u32.u64 %0, t; }" : "=r"(a) : "l"(p));
    return a;
}
__device__ __forceinline__ void bsplit(float x, __nv_bfloat16& h, __nv_bfloat16& l){
    h = __float2bfloat16(x);
    l = __float2bfloat16(x - __bfloat162float(h));
}
__device__ __forceinline__ u32 bpack(__nv_bfloat16 a, __nv_bfloat16 b){
    return (u32)__bfloat16_as_ushort(a) | ((u32)__bfloat16_as_ushort(b) << 16);
}
__device__ __forceinline__ void bsplit2(float x0, float x1, u32& hi, u32& lo){
    __nv_bfloat16 h0, l0, h1, l1;
    bsplit(x0, h0, l0); bsplit(x1, h1, l1);
    hi = bpack(h0, h1); lo = bpack(l0, l1);
}
__device__ __forceinline__ void mma16816(float c[4], const u32 a[4], u32 b0, u32 b1){
    asm volatile(
        "mma.sync.aligned.m16n8k16.row.col.f32.bf16.bf16.f32 "
        "{%0,%1,%2,%3}, {%4,%5,%6,%7}, {%8,%9}, {%0,%1,%2,%3};"
        : "+f"(c[0]), "+f"(c[1]), "+f"(c[2]), "+f"(c[3])
        : "r"(a[0]), "r"(a[1]), "r"(a[2]), "r"(a[3]), "r"(b0), "r"(b1));
}
__device__ __forceinline__ void ldsm4(u32 r[4], u32 saddr){
    asm volatile("ldmatrix.sync.aligned.m8n8.x4.shared.b16 {%0,%1,%2,%3}, [%4];"
        : "=r"(r[0]), "=r"(r[1]), "=r"(r[2]), "=r"(r[3]) : "r"(saddr));
}

// ---------------- smem layout (bytes) ----------------
// One filter block; the second filter lives at +FSTRIDE.
#define PW1 80
#define PW2 272
#define O_W1H 0u
#define O_W1L 10240u
#define O_WEH 20480u
#define O_WEL 30720u
#define O_W2H 40960u
#define O_W2L 75776u
#define O_BR1 110592u
#define O_BR2 111104u
#define O_BE2 111616u
#define O_BE1 112128u
#define O_WE1 112256u
#define FSTRIDE 112768u
#define NWARPS 12
#define EDGE_SMEM (2 * 112768)   // 225536

__global__ __launch_bounds__(384, 1)
void edge_filter_mma(const float* __restrict__ evf,
                     const int*   __restrict__ senders,
                     const int*   __restrict__ receivers,
                     const float* __restrict__ lengths,
                     const float* __restrict__ fi_w1, const float* __restrict__ fi_b1,
                     const float* __restrict__ fi_w2, const float* __restrict__ fi_b2,
                     const float* __restrict__ fi_e1, const float* __restrict__ fi_eb1,
                     const float* __restrict__ fi_e2, const float* __restrict__ fi_eb2,
                     const float* __restrict__ fe_w1, const float* __restrict__ fe_b1,
                     const float* __restrict__ fe_w2, const float* __restrict__ fe_b2,
                     const float* __restrict__ fe_e1, const float* __restrict__ fe_eb1,
                     const float* __restrict__ fe_e2, const float* __restrict__ fe_eb2,
                     float* __restrict__ out_i, float* __restrict__ out_e, int E)
{
    extern __shared__ char smc[];
    const u32 sbase = smem_u32(smc);
    const int tid  = threadIdx.x;
    const int lane = tid & 31;
    const int warp = tid >> 5;

    // ---- preload both filters' weights (transposed [n][k] + hi/lo split) ----
    {
        const float* W1[2] = {fi_w1, fe_w1};
        const float* WE2[2] = {fi_e2, fe_e2};
        const float* W2[2] = {fi_w2, fe_w2};
        const float* B1[2] = {fi_b1, fe_b1};
        const float* B2[2] = {fi_b2, fe_b2};
        const float* EB2[2] = {fi_eb2, fe_eb2};
        const float* EB1[2] = {fi_eb1, fe_eb1};
        const float* WE1[2] = {fi_e1, fe_e1};
        #pragma unroll
        for (int f = 0; f < 2; f++) {
            char* base = smc + f * FSTRIDE;
            for (int i = tid; i < 4096; i += 384) {          // wr1 [32k][128n]
                int n = i & 127, k = i >> 7;
                __nv_bfloat16 h, l; bsplit(W1[f][k * 128 + n], h, l);
                *(__nv_bfloat16*)(base + O_W1H + n * PW1 + k * 2) = h;
                *(__nv_bfloat16*)(base + O_W1L + n * PW1 + k * 2) = l;
            }
            for (int i = tid; i < 4096; i += 384) {          // we2 [32k][128n]
                int n = i & 127, k = i >> 7;
                __nv_bfloat16 h, l; bsplit(WE2[f][k * 128 + n], h, l);
                *(__nv_bfloat16*)(base + O_WEH + n * PW1 + k * 2) = h;
                *(__nv_bfloat16*)(base + O_WEL + n * PW1 + k * 2) = l;
            }
            for (int i = tid; i < 16384; i += 384) {         // wr2 [128k][128n]
                int n = i & 127, k = i >> 7;
                __nv_bfloat16 h, l; bsplit(W2[f][k * 128 + n], h, l);
                *(__nv_bfloat16*)(base + O_W2H + n * PW2 + k * 2) = h;
                *(__nv_bfloat16*)(base + O_W2L + n * PW2 + k * 2) = l;
            }
            if (tid < 128) {
                ((float*)(base + O_BR1))[tid] = B1[f][tid];
                ((float*)(base + O_BR2))[tid] = B2[f][tid];
                ((float*)(base + O_BE2))[tid] = EB2[f][tid];
                ((float*)(base + O_WE1))[tid] = WE1[f][tid];
            }
            if (tid < 32) ((float*)(base + O_BE1))[tid] = EB1[f][tid];
        }
    }
    __syncthreads();

    const int qk = lane & 3;
    const int rr = lane >> 2;
    const float STEP = 5.0f / 31.0f;
    const float GAMMA = 0.5f * (31.0f / 5.0f) * (31.0f / 5.0f);

    // ldmatrix lane-constant address parts (filter-0 bases; +fo per pass)
    const u32 lrow  = (u32)((lane & 7) + ((lane & 16) >> 1));
    const u32 lcolB = (u32)((lane & 8) << 1);
    const u32 bW1H = sbase + O_W1H + lrow * PW1 + lcolB;
    const u32 bW1L = sbase + O_W1L + lrow * PW1 + lcolB;
    const u32 bWEH = sbase + O_WEH + lrow * PW1 + lcolB;
    const u32 bWEL = sbase + O_WEL + lrow * PW1 + lcolB;
    const u32 bW2H = sbase + O_W2H + lrow * PW2 + lcolB;
    const u32 bW2L = sbase + O_W2L + lrow * PW2 + lcolB;

    const int nGroups = (E + 15) >> 4;
    const int gstride = gridDim.x * NWARPS;

    for (int g = blockIdx.x * NWARPS + warp; g < nGroups; g += gstride) {
        const int ebase = g * 16;

        // ---- gather + invariants: ONCE per tile, shared by both filters ----
        float q0f, q1f, q2f, q3f;
        {
            int m = lane >> 1, half = lane & 1;
            int gm = ebase + m; if (gm >= E) gm = E - 1;
            int sm_ = senders[gm], rm_ = receivers[gm];
            const float4* ps = (const float4*)(evf + (size_t)sm_ * 16 + half * 8);
            const float4* pr = (const float4*)(evf + (size_t)rm_ * 16 + half * 8);
            float4 sa = ps[0], sb = ps[1], ra = pr[0], rb = pr[1];
            float d[8];
            d[0] = sa.x - ra.x; d[1] = sa.y - ra.y; d[2] = sa.z - ra.z; d[3] = sa.w - ra.w;
            d[4] = sb.x - rb.x; d[5] = sb.y - rb.y; d[6] = sb.z - rb.z; d[7] = sb.w - rb.w;
            #pragma unroll
            for (int i = 0; i < 8; i++) d[i] *= d[i];
            float q0, q1, q2p, q3p;
            if (half == 0) {
                q0 = d[0]; q1 = d[1] + d[2] + d[3];
                q2p = d[4] + d[5] + d[6] + d[7]; q3p = 0.0f;
            } else {
                q0 = 0.0f; q1 = 0.0f; q2p = d[0];
                q3p = d[1] + d[2] + d[3] + d[4] + d[5] + d[6] + d[7];
            }
            q0f = q0 + __shfl_xor_sync(FULLMASK, q0, 1);
            q1f = q1 + __shfl_xor_sync(FULLMASK, q1, 1);
            q2f = q2p + __shfl_xor_sync(FULLMASK, q2p, 1);
            q3f = q3p + __shfl_xor_sync(FULLMASK, q3p, 1);
        }
        const int src0 = rr << 1, src8 = (rr << 1) + 16;
        float i0q[4], i8q[4];
        i0q[0] = __shfl_sync(FULLMASK, q0f, src0);
        i0q[1] = __shfl_sync(FULLMASK, q1f, src0);
        i0q[2] = __shfl_sync(FULLMASK, q2f, src0);
        i0q[3] = __shfl_sync(FULLMASK, q3f, src0);
        i8q[0] = __shfl_sync(FULLMASK, q0f, src8);
        i8q[1] = __shfl_sync(FULLMASK, q1f, src8);
        i8q[2] = __shfl_sync(FULLMASK, q2f, src8);
        i8q[3] = __shfl_sync(FULLMASK, q3f, src8);

        int ge0 = ebase + rr;      if (ge0 >= E) ge0 = E - 1;
        int ge8 = ebase + rr + 8;  if (ge8 >= E) ge8 = E - 1;
        const float lm0 = lengths[ge0], lm8 = lengths[ge8];

        const int e0 = ebase + rr, e1_ = ebase + rr + 8;

        // ============ two filter passes over the same tile ============
        #pragma unroll 1
        for (int f = 0; f < 2; f++) {
            const u32 fo = (u32)f * FSTRIDE;
            const char* fbase = smc + fo;
            const float* br1s = (const float*)(fbase + O_BR1);
            const float* br2s = (const float*)(fbase + O_BR2);
            const float* be2s = (const float*)(fbase + O_BE2);
            const float* be1s = (const float*)(fbase + O_BE1);
            const float* we1s = (const float*)(fbase + O_WE1);
            float* outw = f ? out_e : out_i;

            // ---- e1 A-fragments ----
            u32 eAh[2][4], eAl[2][4];
            #pragma unroll
            for (int ks = 0; ks < 2; ks++) {
                const int kb = 2 * qk + 16 * ks;
                float ev[8];
                const int kk[4] = {kb, kb + 1, kb + 8, kb + 9};
                #pragma unroll
                for (int j = 0; j < 4; j++) {
                    int k = kk[j];
                    float w0 = we1s[k], w1 = we1s[32 + k], w2 = we1s[64 + k], w3 = we1s[96 + k];
                    float bk = be1s[k];
                    float a0 = bk, a8 = bk;
                    a0 = fmaf(i0q[0], w0, a0); a0 = fmaf(i0q[1], w1, a0);
                    a0 = fmaf(i0q[2], w2, a0); a0 = fmaf(i0q[3], w3, a0);
                    a8 = fmaf(i8q[0], w0, a8); a8 = fmaf(i8q[1], w1, a8);
                    a8 = fmaf(i8q[2], w2, a8); a8 = fmaf(i8q[3], w3, a8);
                    ev[j * 2]     = silu_f(a0);
                    ev[j * 2 + 1] = silu_f(a8);
                }
                bsplit2(ev[0], ev[2], eAh[ks][0], eAl[ks][0]);
                bsplit2(ev[1], ev[3], eAh[ks][1], eAl[ks][1]);
                bsplit2(ev[4], ev[6], eAh[ks][2], eAl[ks][2]);
                bsplit2(ev[5], ev[7], eAh[ks][3], eAl[ks][3]);
            }

            // ============ stage 1: h1pre = rbf @ wr1 ============
            float C1[16][4];
            #pragma unroll
            for (int nf = 0; nf < 16; nf++)
                { C1[nf][0] = 0.f; C1[nf][1] = 0.f; C1[nf][2] = 0.f; C1[nf][3] = 0.f; }

            #pragma unroll
            for (int ks = 0; ks < 2; ks++) {
                const int kb = 2 * qk + 16 * ks;
                float c0 = (float)kb * STEP, c1 = (float)(kb + 1) * STEP;
                float c8 = (float)(kb + 8) * STEP, c9 = (float)(kb + 9) * STEP;
                float t;
                u32 ah[4], al[4];
                t = lm0 - c0; float v0 = __expf(-GAMMA * t * t);
                t = lm0 - c1; float v1 = __expf(-GAMMA * t * t);
                t = lm8 - c0; float v2 = __expf(-GAMMA * t * t);
                t = lm8 - c1; float v3 = __expf(-GAMMA * t * t);
                t = lm0 - c8; float v4 = __expf(-GAMMA * t * t);
                t = lm0 - c9; float v5 = __expf(-GAMMA * t * t);
                t = lm8 - c8; float v6 = __expf(-GAMMA * t * t);
                t = lm8 - c9; float v7 = __expf(-GAMMA * t * t);
                bsplit2(v0, v1, ah[0], al[0]); bsplit2(v2, v3, ah[1], al[1]);
                bsplit2(v4, v5, ah[2], al[2]); bsplit2(v6, v7, ah[3], al[3]);
                #pragma unroll
                for (int p = 0; p < 8; p++) {
                    u32 bh[4], bl[4];
                    ldsm4(bh, bW1H + fo + (u32)(p * 16 * PW1 + ks * 32));
                    ldsm4(bl, bW1L + fo + (u32)(p * 16 * PW1 + ks * 32));
                    mma16816(C1[2*p],   ah, bh[0], bh[1]);
                    mma16816(C1[2*p+1], ah, bh[2], bh[3]);
                    mma16816(C1[2*p],   al, bh[0], bh[1]);
                    mma16816(C1[2*p+1], al, bh[2], bh[3]);
                    mma16816(C1[2*p],   ah, bl[0], bl[1]);
                    mma16816(C1[2*p+1], ah, bl[2], bl[3]);
                }
            }
            // h1 = silu(C1 + br1), kept in registers
            #pragma unroll
            for (int nf = 0; nf < 16; nf++) {
                int c = nf * 8 + 2 * qk;
                float2 b1v = *(const float2*)&br1s[c];
                C1[nf][0] = silu_f(C1[nf][0] + b1v.x);
                C1[nf][1] = silu_f(C1[nf][1] + b1v.y);
                C1[nf][2] = silu_f(C1[nf][2] + b1v.x);
                C1[nf][3] = silu_f(C1[nf][3] + b1v.y);
            }

            // ============ stage 2: h2pre = h1 @ wr2 ============
            float C2[16][4];
            #pragma unroll
            for (int nf = 0; nf < 16; nf++)
                { C2[nf][0] = 0.f; C2[nf][1] = 0.f; C2[nf][2] = 0.f; C2[nf][3] = 0.f; }

            #pragma unroll
            for (int ks = 0; ks < 8; ks++) {
                u32 ah[4], al[4];
                bsplit2(C1[2*ks][0],   C1[2*ks][1],   ah[0], al[0]);
                bsplit2(C1[2*ks][2],   C1[2*ks][3],   ah[1], al[1]);
                bsplit2(C1[2*ks+1][0], C1[2*ks+1][1], ah[2], al[2]);
                bsplit2(C1[2*ks+1][2], C1[2*ks+1][3], ah[3], al[3]);
                #pragma unroll
                for (int p = 0; p < 8; p++) {
                    u32 bh[4], bl[4];
                    ldsm4(bh, bW2H + fo + (u32)(p * 16 * PW2 + ks * 32));
                    ldsm4(bl, bW2L + fo + (u32)(p * 16 * PW2 + ks * 32));
                    mma16816(C2[2*p],   ah, bh[0], bh[1]);
                    mma16816(C2[2*p+1], ah, bh[2], bh[3]);
                    mma16816(C2[2*p],   al, bh[0], bh[1]);
                    mma16816(C2[2*p+1], al, bh[2], bh[3]);
                    mma16816(C2[2*p],   ah, bl[0], bl[1]);
                    mma16816(C2[2*p+1], ah, bl[2], bl[3]);
                }
            }

            // ============ stage E: e2pre = e1 @ we2 ============
            float CE[16][4];
            #pragma unroll
            for (int nf = 0; nf < 16; nf++)
                { CE[nf][0] = 0.f; CE[nf][1] = 0.f; CE[nf][2] = 0.f; CE[nf][3] = 0.f; }

            #pragma unroll
            for (int ks = 0; ks < 2; ks++) {
                #pragma unroll
                for (int p = 0; p < 8; p++) {
                    u32 bh[4], bl[4];
                    ldsm4(bh, bWEH + fo + (u32)(p * 16 * PW1 + ks * 32));
                    ldsm4(bl, bWEL + fo + (u32)(p * 16 * PW1 + ks * 32));
                    mma16816(CE[2*p],   eAh[ks], bh[0], bh[1]);
                    mma16816(CE[2*p+1], eAh[ks], bh[2], bh[3]);
                    mma16816(CE[2*p],   eAl[ks], bh[0], bh[1]);
                    mma16816(CE[2*p+1], eAl[ks], bh[2], bh[3]);
                    mma16816(CE[2*p],   eAh[ks], bl[0], bl[1]);
                    mma16816(CE[2*p+1], eAh[ks], bl[2], bl[3]);
                }
            }

            // ============ epilogue ============
            float* p0 = outw + (size_t)e0 * 128;
            float* p1 = outw + (size_t)e1_ * 128;
            #pragma unroll
            for (int nf = 0; nf < 16; nf++) {
                int c = nf * 8 + 2 * qk;
                float2 b2 = *(const float2*)&br2s[c];
                float2 be = *(const float2*)&be2s[c];
                if (e0 < E) {
                    float2 o;
                    o.x = silu_f(C2[nf][0] + b2.x) + silu_f(CE[nf][0] + be.x);
                    o.y = silu_f(C2[nf][1] + b2.y) + silu_f(CE[nf][1] + be.y);
                    *(float2*)&p0[c] = o;
                }
                if (e1_ < E) {
                    float2 o;
                    o.x = silu_f(C2[nf][2] + b2.x) + silu_f(CE[nf][2] + be.x);
                    o.y = silu_f(C2[nf][3] + b2.y) + silu_f(CE[nf][3] + be.y);
                    *(float2*)&p1[c] = o;
                }
            }
        }
    }
}

// ---------------------------------------------------------------------------
// Node kernel (unchanged, ~134us)
// ---------------------------------------------------------------------------
__global__ __launch_bounds__(264, 2)
void node_kernel(const float* __restrict__ inv_f, const float* __restrict__ ev_f,
                 const float* __restrict__ w_int, const float* __restrict__ b_int,
                 float* __restrict__ out_inv, float* __restrict__ out_ev, int N)
{
    extern __shared__ float sm[];
    float* Wsh = sm;
    float* bsh = Wsh + 17424;
    float* xs  = bsh + 132;
    float* aev = xs + 4224;

    const int tx  = threadIdx.x;
    const int ty  = threadIdx.y;
    const int tid = tx + 33 * ty;
    const int NT  = 264;

    for (int i = tid; i < 17424; i += NT) Wsh[i] = w_int[i];
    if (tid < 132) bsh[tid] = b_int[tid];
    __syncthreads();

    const int nTiles = (N + 31) / 32;
    for (int tile = blockIdx.x; tile < nTiles; tile += gridDim.x) {
        const int base = tile * 32;

        for (int i = tid; i < 32 * 132; i += NT) {
            int l = i / 132, c = i % 132;
            int n = base + l;
            float v = 0.0f;
            if (n < N) {
                if (c < 128) {
                    v = 2.0f * inv_f[(size_t)n * 128 + c];
                } else {
                    const int st[5] = {0, 1, 4, 9, 16};
                    int s = c - 128;
                    float acc = 0.0f;
                    for (int k = st[s]; k < st[s + 1]; k++) {
                        float a = 2.0f * ev_f[(size_t)n * 16 + k];
                        acc = fmaf(a, a, acc);
                    }
                    v = acc;
                }
            }
            xs[l * 132 + c] = v;
        }
        for (int i = tid; i < 512; i += NT) {
            int l = i / 16, k = i % 16;
            int n = base + l;
            aev[i] = (n < N) ? 2.0f * ev_f[(size_t)n * 16 + k] : 0.0f;
        }
        __syncthreads();

        const int c0 = tx * 4;
        float acc[4][4];
        #pragma unroll
        for (int i = 0; i < 4; i++)
            #pragma unroll
            for (int k = 0; k < 4; k++) acc[i][k] = 0.0f;

        #pragma unroll 4
        for (int j = 0; j < 132; j++) {
            float4 w4 = *(const float4*)&Wsh[j * 132 + c0];
            #pragma unroll
            for (int i = 0; i < 4; i++) {
                float xv = xs[(ty * 4 + i) * 132 + j];
                acc[i][0] = fmaf(xv, w4.x, acc[i][0]);
                acc[i][1] = fmaf(xv, w4.y, acc[i][1]);
                acc[i][2] = fmaf(xv, w4.z, acc[i][2]);
                acc[i][3] = fmaf(xv, w4.w, acc[i][3]);
            }
        }

        const float4 bv = *(const float4*)&bsh[c0];
        #pragma unroll
        for (int i = 0; i < 4; i++) {
            int n = base + ty * 4 + i;
            if (n >= N) continue;
            float t0 = acc[i][0] + bv.x;
            float t1 = acc[i][1] + bv.y;
            float t2 = acc[i][2] + bv.z;
            float t3 = acc[i][3] + bv.w;
            if (tx < 32) {
                float4 o;
                o.x = xs[(ty * 4 + i) * 132 + c0 + 0] + t0;
                o.y = xs[(ty * 4 + i) * 132 + c0 + 1] + t1;
                o.z = xs[(ty * 4 + i) * 132 + c0 + 2] + t2;
                o.w = xs[(ty * 4 + i) * 132 + c0 + 3] + t3;
                *(float4*)&out_inv[(size_t)n * 128 + c0] = o;
            } else {
                float tb[4] = {t0, t1, t2, t3};
                const int SEG[16] = {0,1,1,1,2,2,2,2,2,3,3,3,3,3,3,3};
                #pragma unroll
                for (int k = 0; k < 16; k++) {
                    out_ev[(size_t)n * 16 + k] =
                        aev[(ty * 4 + i) * 16 + k] * (1.0f + tb[SEG[k]]);
                }
            }
        }
        __syncthreads();
    }
}

static const int NODE_SMEM = 22292 * 4;

extern "C" void kernel_launch(void* const* d_in, const int* in_sizes, int n_in,
                              void* d_out, int out_size)
{
    const float* inv_f     = (const float*)d_in[0];
    const float* ev_f      = (const float*)d_in[1];
    const int*   senders   = (const int*)  d_in[2];
    const int*   receivers = (const int*)  d_in[3];
    const float* lengths   = (const float*)d_in[5];

    const float* fi_rbf_w1 = (const float*)d_in[7];
    const float* fi_rbf_b1 = (const float*)d_in[8];
    const float* fi_rbf_w2 = (const float*)d_in[9];
    const float* fi_rbf_b2 = (const float*)d_in[10];
    const float* fi_ev_w1  = (const float*)d_in[11];
    const float* fi_ev_b1  = (const float*)d_in[12];
    const float* fi_ev_w2  = (const float*)d_in[13];
    const float* fi_ev_b2  = (const float*)d_in[14];
    const float* fe_rbf_w1 = (const float*)d_in[15];
    const float* fe_rbf_b1 = (const float*)d_in[16];
    const float* fe_rbf_w2 = (const float*)d_in[17];
    const float* fe_rbf_b2 = (const float*)d_in[18];
    const float* fe_ev_w1  = (const float*)d_in[19];
    const float* fe_ev_b1  = (const float*)d_in[20];
    const float* fe_ev_w2  = (const float*)d_in[21];
    const float* fe_ev_b2  = (const float*)d_in[22];
    const float* w_int     = (const float*)d_in[23];
    const float* b_int     = (const float*)d_in[24];

    const int N = in_sizes[0] / 128;
    const int E = in_sizes[2];

    float* out     = (float*)d_out;
    float* out_inv = out;
    float* out_ev  = out + (size_t)N * 128;
    float* fw_inv  = out + (size_t)N * 144;
    float* fw_ev   = fw_inv + (size_t)E * 128;

    cudaFuncSetAttribute(node_kernel,
                         cudaFuncAttributeMaxDynamicSharedMemorySize, NODE_SMEM);
    cudaFuncSetAttribute(edge_filter_mma,
                         cudaFuncAttributeMaxDynamicSharedMemorySize, EDGE_SMEM);

    edge_filter_mma<<<148, 384, EDGE_SMEM>>>(
        ev_f, senders, receivers, lengths,
        fi_rbf_w1, fi_rbf_b1, fi_rbf_w2, fi_rbf_b2,
        fi_ev_w1,  fi_ev_b1,  fi_ev_w2,  fi_ev_b2,
        fe_rbf_w1, fe_rbf_b1, fe_rbf_w2, fe_rbf_b2,
        fe_ev_w1,  fe_ev_b1,  fe_ev_w2,  fe_ev_b2,
        fw_inv, fw_ev, E);

    node_kernel<<<304, dim3(33, 8), NODE_SMEM>>>(
        inv_f, ev_f, w_int, b_int, out_inv, out_ev, N);
}

// round 16
// speedup vs baseline: 1.2041x; 1.2041x over previous
#include <cuda_runtime.h>
#include <cuda_fp16.h>

typedef unsigned int u32;
#define FULLMASK 0xffffffffu

__device__ __forceinline__ float silu_f(float x){
    return __fdividef(x, 1.0f + __expf(-x));
}

__device__ __forceinline__ u32 smem_u32(const void* p){
    u32 a;
    asm("{ .reg .u64 t; cvta.to.shared.u64 t, %1; cvt.u32.u64 %0, t; }" : "=r"(a) : "l"(p));
    return a;
}
__device__ __forceinline__ u32 hpack(__half a, __half b){
    return (u32)__half_as_ushort(a) | ((u32)__half_as_ushort(b) << 16);
}
// fp16 2-way split of two floats -> packed (Ah0,Ah1), (Al0,Al1)
__device__ __forceinline__ void hsplit2(float x0, float x1, u32& hi, u32& lo){
    __half h0 = __float2half_rn(x0);
    __half h1 = __float2half_rn(x1);
    __half l0 = __float2half_rn(x0 - __half2float(h0));
    __half l1 = __float2half_rn(x1 - __half2float(h1));
    hi = hpack(h0, h1); lo = hpack(l0, l1);
}
__device__ __forceinline__ void mma16816h(float c[4], const u32 a[4], u32 b0, u32 b1){
    asm volatile(
        "mma.sync.aligned.m16n8k16.row.col.f32.f16.f16.f32 "
        "{%0,%1,%2,%3}, {%4,%5,%6,%7}, {%8,%9}, {%0,%1,%2,%3};"
        : "+f"(c[0]), "+f"(c[1]), "+f"(c[2]), "+f"(c[3])
        : "r"(a[0]), "r"(a[1]), "r"(a[2]), "r"(a[3]), "r"(b0), "r"(b1));
}
__device__ __forceinline__ void ldsm4(u32 r[4], u32 saddr){
    asm volatile("ldmatrix.sync.aligned.m8n8.x4.shared.b16 {%0,%1,%2,%3}, [%4];"
        : "=r"(r[0]), "=r"(r[1]), "=r"(r[2]), "=r"(r[3]) : "r"(saddr));
}

// ---------------- smem layout (bytes), per filter; filter 1 at +FSTRIDE ----
#define PW1 80
#define PW2 272
#define O_W1  0u        // 128n * 80  = 10240  (wr1, fp16 single)
#define O_WE  10240u    // 128n * 80  = 10240  (we2, fp16 single)
#define O_W2  20480u    // 128n * 272 = 34816  (wr2, fp16 single)
#define O_BR1 55296u
#define O_BR2 55808u
#define O_BE2 56320u
#define O_BE1 56832u
#define O_WE1 56960u    // 512
#define FSTRIDE 57472u
#define NWARPS 12
#define EDGE_SMEM (2 * 57472)   // 114944

__global__ __launch_bounds__(384, 1)
void edge_filter_mma(const float* __restrict__ evf,
                     const int*   __restrict__ senders,
                     const int*   __restrict__ receivers,
                     const float* __restrict__ lengths,
                     const float* __restrict__ fi_w1, const float* __restrict__ fi_b1,
                     const float* __restrict__ fi_w2, const float* __restrict__ fi_b2,
                     const float* __restrict__ fi_e1, const float* __restrict__ fi_eb1,
                     const float* __restrict__ fi_e2, const float* __restrict__ fi_eb2,
                     const float* __restrict__ fe_w1, const float* __restrict__ fe_b1,
                     const float* __restrict__ fe_w2, const float* __restrict__ fe_b2,
                     const float* __restrict__ fe_e1, const float* __restrict__ fe_eb1,
                     const float* __restrict__ fe_e2, const float* __restrict__ fe_eb2,
                     float* __restrict__ out_i, float* __restrict__ out_e, int E)
{
    extern __shared__ char smc[];
    const u32 sbase = smem_u32(smc);
    const int tid  = threadIdx.x;
    const int lane = tid & 31;
    const int warp = tid >> 5;

    // ---- preload both filters' weights (transposed [n][k], fp16 single) ----
    {
        const float* W1[2]  = {fi_w1, fe_w1};
        const float* WE2[2] = {fi_e2, fe_e2};
        const float* W2[2]  = {fi_w2, fe_w2};
        const float* B1[2]  = {fi_b1, fe_b1};
        const float* B2[2]  = {fi_b2, fe_b2};
        const float* EB2[2] = {fi_eb2, fe_eb2};
        const float* EB1[2] = {fi_eb1, fe_eb1};
        const float* WE1[2] = {fi_e1, fe_e1};
        #pragma unroll
        for (int f = 0; f < 2; f++) {
            char* base = smc + f * FSTRIDE;
            for (int i = tid; i < 4096; i += 384) {          // wr1 [32k][128n]
                int n = i & 127, k = i >> 7;
                *(__half*)(base + O_W1 + n * PW1 + k * 2) = __float2half_rn(W1[f][k * 128 + n]);
            }
            for (int i = tid; i < 4096; i += 384) {          // we2 [32k][128n]
                int n = i & 127, k = i >> 7;
                *(__half*)(base + O_WE + n * PW1 + k * 2) = __float2half_rn(WE2[f][k * 128 + n]);
            }
            for (int i = tid; i < 16384; i += 384) {         // wr2 [128k][128n]
                int n = i & 127, k = i >> 7;
                *(__half*)(base + O_W2 + n * PW2 + k * 2) = __float2half_rn(W2[f][k * 128 + n]);
            }
            if (tid < 128) {
                ((float*)(base + O_BR1))[tid] = B1[f][tid];
                ((float*)(base + O_BR2))[tid] = B2[f][tid];
                ((float*)(base + O_BE2))[tid] = EB2[f][tid];
                ((float*)(base + O_WE1))[tid] = WE1[f][tid];
            }
            if (tid < 32) ((float*)(base + O_BE1))[tid] = EB1[f][tid];
        }
    }
    __syncthreads();

    const int qk = lane & 3;
    const int rr = lane >> 2;
    const float STEP = 5.0f / 31.0f;
    const float GAMMA = 0.5f * (31.0f / 5.0f) * (31.0f / 5.0f);

    // ldmatrix lane-constant address parts (filter-0 bases; +fo per pass)
    const u32 lrow  = (u32)((lane & 7) + ((lane & 16) >> 1));
    const u32 lcolB = (u32)((lane & 8) << 1);
    const u32 bW1 = sbase + O_W1 + lrow * PW1 + lcolB;
    const u32 bWE = sbase + O_WE + lrow * PW1 + lcolB;
    const u32 bW2 = sbase + O_W2 + lrow * PW2 + lcolB;

    const int nGroups = (E + 15) >> 4;
    const int gstride = gridDim.x * NWARPS;

    for (int g = blockIdx.x * NWARPS + warp; g < nGroups; g += gstride) {
        const int ebase = g * 16;

        // ---- gather + invariants: once per tile, shared by both filters ----
        float q0f, q1f, q2f, q3f;
        {
            int m = lane >> 1, half = lane & 1;
            int gm = ebase + m; if (gm >= E) gm = E - 1;
            int sm_ = senders[gm], rm_ = receivers[gm];
            const float4* ps = (const float4*)(evf + (size_t)sm_ * 16 + half * 8);
            const float4* pr = (const float4*)(evf + (size_t)rm_ * 16 + half * 8);
            float4 sa = ps[0], sb = ps[1], ra = pr[0], rb = pr[1];
            float d[8];
            d[0] = sa.x - ra.x; d[1] = sa.y - ra.y; d[2] = sa.z - ra.z; d[3] = sa.w - ra.w;
            d[4] = sb.x - rb.x; d[5] = sb.y - rb.y; d[6] = sb.z - rb.z; d[7] = sb.w - rb.w;
            #pragma unroll
            for (int i = 0; i < 8; i++) d[i] *= d[i];
            float q0, q1, q2p, q3p;
            if (half == 0) {
                q0 = d[0]; q1 = d[1] + d[2] + d[3];
                q2p = d[4] + d[5] + d[6] + d[7]; q3p = 0.0f;
            } else {
                q0 = 0.0f; q1 = 0.0f; q2p = d[0];
                q3p = d[1] + d[2] + d[3] + d[4] + d[5] + d[6] + d[7];
            }
            q0f = q0 + __shfl_xor_sync(FULLMASK, q0, 1);
            q1f = q1 + __shfl_xor_sync(FULLMASK, q1, 1);
            q2f = q2p + __shfl_xor_sync(FULLMASK, q2p, 1);
            q3f = q3p + __shfl_xor_sync(FULLMASK, q3p, 1);
        }
        const int src0 = rr << 1, src8 = (rr << 1) + 16;
        float i0q[4], i8q[4];
        i0q[0] = __shfl_sync(FULLMASK, q0f, src0);
        i0q[1] = __shfl_sync(FULLMASK, q1f, src0);
        i0q[2] = __shfl_sync(FULLMASK, q2f, src0);
        i0q[3] = __shfl_sync(FULLMASK, q3f, src0);
        i8q[0] = __shfl_sync(FULLMASK, q0f, src8);
        i8q[1] = __shfl_sync(FULLMASK, q1f, src8);
        i8q[2] = __shfl_sync(FULLMASK, q2f, src8);
        i8q[3] = __shfl_sync(FULLMASK, q3f, src8);

        int ge0 = ebase + rr;      if (ge0 >= E) ge0 = E - 1;
        int ge8 = ebase + rr + 8;  if (ge8 >= E) ge8 = E - 1;
        const float lm0 = lengths[ge0], lm8 = lengths[ge8];

        const int e0 = ebase + rr, e1_ = ebase + rr + 8;

        // ============ two filter passes over the same tile ============
        #pragma unroll 1
        for (int f = 0; f < 2; f++) {
            const u32 fo = (u32)f * FSTRIDE;
            const char* fbase = smc + fo;
            const float* br1s = (const float*)(fbase + O_BR1);
            const float* br2s = (const float*)(fbase + O_BR2);
            const float* be2s = (const float*)(fbase + O_BE2);
            const float* be1s = (const float*)(fbase + O_BE1);
            const float* we1s = (const float*)(fbase + O_WE1);
            float* outw = f ? out_e : out_i;

            // ---- e1 A-fragments (fp16 2-term) ----
            u32 eAh[2][4], eAl[2][4];
            #pragma unroll
            for (int ks = 0; ks < 2; ks++) {
                const int kb = 2 * qk + 16 * ks;
                float ev[8];
                const int kk[4] = {kb, kb + 1, kb + 8, kb + 9};
                #pragma unroll
                for (int j = 0; j < 4; j++) {
                    int k = kk[j];
                    float w0 = we1s[k], w1 = we1s[32 + k], w2 = we1s[64 + k], w3 = we1s[96 + k];
                    float bk = be1s[k];
                    float a0 = bk, a8 = bk;
                    a0 = fmaf(i0q[0], w0, a0); a0 = fmaf(i0q[1], w1, a0);
                    a0 = fmaf(i0q[2], w2, a0); a0 = fmaf(i0q[3], w3, a0);
                    a8 = fmaf(i8q[0], w0, a8); a8 = fmaf(i8q[1], w1, a8);
                    a8 = fmaf(i8q[2], w2, a8); a8 = fmaf(i8q[3], w3, a8);
                    ev[j * 2]     = silu_f(a0);
                    ev[j * 2 + 1] = silu_f(a8);
                }
                hsplit2(ev[0], ev[2], eAh[ks][0], eAl[ks][0]);
                hsplit2(ev[1], ev[3], eAh[ks][1], eAl[ks][1]);
                hsplit2(ev[4], ev[6], eAh[ks][2], eAl[ks][2]);
                hsplit2(ev[5], ev[7], eAh[ks][3], eAl[ks][3]);
            }

            // ============ stage 1: h1pre = rbf @ wr1 ============
            float C1[16][4];
            #pragma unroll
            for (int nf = 0; nf < 16; nf++)
                { C1[nf][0] = 0.f; C1[nf][1] = 0.f; C1[nf][2] = 0.f; C1[nf][3] = 0.f; }

            #pragma unroll
            for (int ks = 0; ks < 2; ks++) {
                const int kb = 2 * qk + 16 * ks;
                float c0 = (float)kb * STEP, c1 = (float)(kb + 1) * STEP;
                float c8 = (float)(kb + 8) * STEP, c9 = (float)(kb + 9) * STEP;
                float t;
                u32 ah[4], al[4];
                t = lm0 - c0; float v0 = __expf(-GAMMA * t * t);
                t = lm0 - c1; float v1 = __expf(-GAMMA * t * t);
                t = lm8 - c0; float v2 = __expf(-GAMMA * t * t);
                t = lm8 - c1; float v3 = __expf(-GAMMA * t * t);
                t = lm0 - c8; float v4 = __expf(-GAMMA * t * t);
                t = lm0 - c9; float v5 = __expf(-GAMMA * t * t);
                t = lm8 - c8; float v6 = __expf(-GAMMA * t * t);
                t = lm8 - c9; float v7 = __expf(-GAMMA * t * t);
                hsplit2(v0, v1, ah[0], al[0]); hsplit2(v2, v3, ah[1], al[1]);
                hsplit2(v4, v5, ah[2], al[2]); hsplit2(v6, v7, ah[3], al[3]);
                #pragma unroll
                for (int p = 0; p < 8; p++) {
                    u32 bh[4];
                    ldsm4(bh, bW1 + fo + (u32)(p * 16 * PW1 + ks * 32));
                    mma16816h(C1[2*p],   ah, bh[0], bh[1]);
                    mma16816h(C1[2*p+1], ah, bh[2], bh[3]);
                    mma16816h(C1[2*p],   al, bh[0], bh[1]);
                    mma16816h(C1[2*p+1], al, bh[2], bh[3]);
                }
            }
            // h1 = silu(C1 + br1), kept in registers
            #pragma unroll
            for (int nf = 0; nf < 16; nf++) {
                int c = nf * 8 + 2 * qk;
                float2 b1v = *(const float2*)&br1s[c];
                C1[nf][0] = silu_f(C1[nf][0] + b1v.x);
                C1[nf][1] = silu_f(C1[nf][1] + b1v.y);
                C1[nf][2] = silu_f(C1[nf][2] + b1v.x);
                C1[nf][3] = silu_f(C1[nf][3] + b1v.y);
            }

            // ============ stage 2: h2pre = h1 @ wr2 (jit fp16 split of C1) ============
            float C2[16][4];
            #pragma unroll
            for (int nf = 0; nf < 16; nf++)
                { C2[nf][0] = 0.f; C2[nf][1] = 0.f; C2[nf][2] = 0.f; C2[nf][3] = 0.f; }

            #pragma unroll
            for (int ks = 0; ks < 8; ks++) {
                u32 ah[4], al[4];
                hsplit2(C1[2*ks][0],   C1[2*ks][1],   ah[0], al[0]);
                hsplit2(C1[2*ks][2],   C1[2*ks][3],   ah[1], al[1]);
                hsplit2(C1[2*ks+1][0], C1[2*ks+1][1], ah[2], al[2]);
                hsplit2(C1[2*ks+1][2], C1[2*ks+1][3], ah[3], al[3]);
                #pragma unroll
                for (int p = 0; p < 8; p++) {
                    u32 bh[4];
                    ldsm4(bh, bW2 + fo + (u32)(p * 16 * PW2 + ks * 32));
                    mma16816h(C2[2*p],   ah, bh[0], bh[1]);
                    mma16816h(C2[2*p+1], ah, bh[2], bh[3]);
                    mma16816h(C2[2*p],   al, bh[0], bh[1]);
                    mma16816h(C2[2*p+1], al, bh[2], bh[3]);
                }
            }

            // ============ stage E: e2pre = e1 @ we2 ============
            float CE[16][4];
            #pragma unroll
            for (int nf = 0; nf < 16; nf++)
                { CE[nf][0] = 0.f; CE[nf][1] = 0.f; CE[nf][2] = 0.f; CE[nf][3] = 0.f; }

            #pragma unroll
            for (int ks = 0; ks < 2; ks++) {
                #pragma unroll
                for (int p = 0; p < 8; p++) {
                    u32 bh[4];
                    ldsm4(bh, bWE + fo + (u32)(p * 16 * PW1 + ks * 32));
                    mma16816h(CE[2*p],   eAh[ks], bh[0], bh[1]);
                    mma16816h(CE[2*p+1], eAh[ks], bh[2], bh[3]);
                    mma16816h(CE[2*p],   eAl[ks], bh[0], bh[1]);
                    mma16816h(CE[2*p+1], eAl[ks], bh[2], bh[3]);
                }
            }

            // ============ epilogue ============
            float* p0 = outw + (size_t)e0 * 128;
            float* p1 = outw + (size_t)e1_ * 128;
            #pragma unroll
            for (int nf = 0; nf < 16; nf++) {
                int c = nf * 8 + 2 * qk;
                float2 b2 = *(const float2*)&br2s[c];
                float2 be = *(const float2*)&be2s[c];
                if (e0 < E) {
                    float2 o;
                    o.x = silu_f(C2[nf][0] + b2.x) + silu_f(CE[nf][0] + be.x);
                    o.y = silu_f(C2[nf][1] + b2.y) + silu_f(CE[nf][1] + be.y);
                    *(float2*)&p0[c] = o;
                }
                if (e1_ < E) {
                    float2 o;
                    o.x = silu_f(C2[nf][2] + b2.x) + silu_f(CE[nf][2] + be.x);
                    o.y = silu_f(C2[nf][3] + b2.y) + silu_f(CE[nf][3] + be.y);
                    *(float2*)&p1[c] = o;
                }
            }
        }
    }
}

// ---------------------------------------------------------------------------
// Node kernel (unchanged, ~134us)
// ---------------------------------------------------------------------------
__global__ __launch_bounds__(264, 2)
void node_kernel(const float* __restrict__ inv_f, const float* __restrict__ ev_f,
                 const float* __restrict__ w_int, const float* __restrict__ b_int,
                 float* __restrict__ out_inv, float* __restrict__ out_ev, int N)
{
    extern __shared__ float sm[];
    float* Wsh = sm;
    float* bsh = Wsh + 17424;
    float* xs  = bsh + 132;
    float* aev = xs + 4224;

    const int tx  = threadIdx.x;
    const int ty  = threadIdx.y;
    const int tid = tx + 33 * ty;
    const int NT  = 264;

    for (int i = tid; i < 17424; i += NT) Wsh[i] = w_int[i];
    if (tid < 132) bsh[tid] = b_int[tid];
    __syncthreads();

    const int nTiles = (N + 31) / 32;
    for (int tile = blockIdx.x; tile < nTiles; tile += gridDim.x) {
        const int base = tile * 32;

        for (int i = tid; i < 32 * 132; i += NT) {
            int l = i / 132, c = i % 132;
            int n = base + l;
            float v = 0.0f;
            if (n < N) {
                if (c < 128) {
                    v = 2.0f * inv_f[(size_t)n * 128 + c];
                } else {
                    const int st[5] = {0, 1, 4, 9, 16};
                    int s = c - 128;
                    float acc = 0.0f;
                    for (int k = st[s]; k < st[s + 1]; k++) {
                        float a = 2.0f * ev_f[(size_t)n * 16 + k];
                        acc = fmaf(a, a, acc);
                    }
                    v = acc;
                }
            }
            xs[l * 132 + c] = v;
        }
        for (int i = tid; i < 512; i += NT) {
            int l = i / 16, k = i % 16;
            int n = base + l;
            aev[i] = (n < N) ? 2.0f * ev_f[(size_t)n * 16 + k] : 0.0f;
        }
        __syncthreads();

        const int c0 = tx * 4;
        float acc[4][4];
        #pragma unroll
        for (int i = 0; i < 4; i++)
            #pragma unroll
            for (int k = 0; k < 4; k++) acc[i][k] = 0.0f;

        #pragma unroll 4
        for (int j = 0; j < 132; j++) {
            float4 w4 = *(const float4*)&Wsh[j * 132 + c0];
            #pragma unroll
            for (int i = 0; i < 4; i++) {
                float xv = xs[(ty * 4 + i) * 132 + j];
                acc[i][0] = fmaf(xv, w4.x, acc[i][0]);
                acc[i][1] = fmaf(xv, w4.y, acc[i][1]);
                acc[i][2] = fmaf(xv, w4.z, acc[i][2]);
                acc[i][3] = fmaf(xv, w4.w, acc[i][3]);
            }
        }

        const float4 bv = *(const float4*)&bsh[c0];
        #pragma unroll
        for (int i = 0; i < 4; i++) {
            int n = base + ty * 4 + i;
            if (n >= N) continue;
            float t0 = acc[i][0] + bv.x;
            float t1 = acc[i][1] + bv.y;
            float t2 = acc[i][2] + bv.z;
            float t3 = acc[i][3] + bv.w;
            if (tx < 32) {
                float4 o;
                o.x = xs[(ty * 4 + i) * 132 + c0 + 0] + t0;
                o.y = xs[(ty * 4 + i) * 132 + c0 + 1] + t1;
                o.z = xs[(ty * 4 + i) * 132 + c0 + 2] + t2;
                o.w = xs[(ty * 4 + i) * 132 + c0 + 3] + t3;
                *(float4*)&out_inv[(size_t)n * 128 + c0] = o;
            } else {
                float tb[4] = {t0, t1, t2, t3};
                const int SEG[16] = {0,1,1,1,2,2,2,2,2,3,3,3,3,3,3,3};
                #pragma unroll
                for (int k = 0; k < 16; k++) {
                    out_ev[(size_t)n * 16 + k] =
                        aev[(ty * 4 + i) * 16 + k] * (1.0f + tb[SEG[k]]);
                }
            }
        }
        __syncthreads();
    }
}

static const int NODE_SMEM = 22292 * 4;

extern "C" void kernel_launch(void* const* d_in, const int* in_sizes, int n_in,
                              void* d_out, int out_size)
{
    const float* inv_f     = (const float*)d_in[0];
    const float* ev_f      = (const float*)d_in[1];
    const int*   senders   = (const int*)  d_in[2];
    const int*   receivers = (const int*)  d_in[3];
    const float* lengths   = (const float*)d_in[5];

    const float* fi_rbf_w1 = (const float*)d_in[7];
    const float* fi_rbf_b1 = (const float*)d_in[8];
    const float* fi_rbf_w2 = (const float*)d_in[9];
    const float* fi_rbf_b2 = (const float*)d_in[10];
    const float* fi_ev_w1  = (const float*)d_in[11];
    const float* fi_ev_b1  = (const float*)d_in[12];
    const float* fi_ev_w2  = (const float*)d_in[13];
    const float* fi_ev_b2  = (const float*)d_in[14];
    const float* fe_rbf_w1 = (const float*)d_in[15];
    const float* fe_rbf_b1 = (const float*)d_in[16];
    const float* fe_rbf_w2 = (const float*)d_in[17];
    const float* fe_rbf_b2 = (const float*)d_in[18];
    const float* fe_ev_w1  = (const float*)d_in[19];
    const float* fe_ev_b1  = (const float*)d_in[20];
    const float* fe_ev_w2  = (const float*)d_in[21];
    const float* fe_ev_b2  = (const float*)d_in[22];
    const float* w_int     = (const float*)d_in[23];
    const float* b_int     = (const float*)d_in[24];

    const int N = in_sizes[0] / 128;
    const int E = in_sizes[2];

    float* out     = (float*)d_out;
    float* out_inv = out;
    float* out_ev  = out + (size_t)N * 128;
    float* fw_inv  = out + (size_t)N * 144;
    float* fw_ev   = fw_inv + (size_t)E * 128;

    cudaFuncSetAttribute(node_kernel,
                         cudaFuncAttributeMaxDynamicSharedMemorySize, NODE_SMEM);
    cudaFuncSetAttribute(edge_filter_mma,
                         cudaFuncAttributeMaxDynamicSharedMemorySize, EDGE_SMEM);

    edge_filter_mma<<<148, 384, EDGE_SMEM>>>(
        ev_f, senders, receivers, lengths,
        fi_rbf_w1, fi_rbf_b1, fi_rbf_w2, fi_rbf_b2,
        fi_ev_w1,  fi_ev_b1,  fi_ev_w2,  fi_ev_b2,
        fe_rbf_w1, fe_rbf_b1, fe_rbf_w2, fe_rbf_b2,
        fe_ev_w1,  fe_ev_b1,  fe_ev_w2,  fe_ev_b2,
        fw_inv, fw_ev, E);

    node_kernel<<<304, dim3(33, 8), NODE_SMEM>>>(
        inv_f, ev_f, w_int, b_int, out_inv, out_ev, N);
}